// round 4
// baseline (speedup 1.0000x reference)
#include <cuda_runtime.h>
#include <cuda_bf16.h>
#include <cstdint>

// Problem shapes (fixed by setup_inputs): B=2048, D=768, P=16384, NP=8
#define D_DIM 768
#define BM 128
#define BN 128
#define BK 32
#define LDSW 40                 // padded smem row stride in bf16 (80B) -> conflict-free ldmatrix/STS
#define KT_ITERS (D_DIM / BK)   // 24

// ---- scratch (no allocations allowed; __device__ globals are the sanctioned path) ----
__device__ __nv_bfloat16 g_qb[2048 * 768];
__device__ __nv_bfloat16 g_pb[16384 * 768];
__device__ float g_scores[(size_t)2048 * 16384];   // 128 MB
__device__ double g_loss_sum;

// ---------------------------------------------------------------------------
__global__ void convert_kernel(const float* __restrict__ q, const float* __restrict__ p,
                               int nq, int ntot) {
    int i = blockIdx.x * blockDim.x + threadIdx.x;
    if (i >= ntot) return;
    if (i < nq) g_qb[i] = __float2bfloat16(q[i]);
    else        g_pb[i - nq] = __float2bfloat16(p[i - nq]);
}

__global__ void init_kernel() { g_loss_sum = 0.0; }

__device__ __forceinline__ unsigned sptr(const void* p) {
    return (unsigned)__cvta_generic_to_shared(p);
}

// ---------------------------------------------------------------------------
// scores = qb @ pb^T  (M=2048, N=16384, K=768), bf16 inputs, fp32 accumulate.
// Block 128x128, 8 warps (2x4), warp tile 64x32, k-chunk 32, double-buffered cp.async.
__global__ __launch_bounds__(256, 2) void gemm_kernel(int P) {
    __shared__ __nv_bfloat16 sA[2][BM * LDSW];
    __shared__ __nv_bfloat16 sB[2][BN * LDSW];

    const int tid  = threadIdx.x;
    const int lane = tid & 31;
    const int warp = tid >> 5;
    const int wm   = warp >> 2;   // 0..1 -> 64 rows
    const int wn   = warp & 3;    // 0..3 -> 32 cols
    const int bm   = blockIdx.y * BM;
    const int bn   = blockIdx.x * BN;

    const __nv_bfloat16* gA = g_qb + (size_t)bm * D_DIM;
    const __nv_bfloat16* gB = g_pb + (size_t)bn * D_DIM;

    float acc[4][4][4];
    #pragma unroll
    for (int a = 0; a < 4; a++)
        #pragma unroll
        for (int b = 0; b < 4; b++)
            #pragma unroll
            for (int c = 0; c < 4; c++) acc[a][b][c] = 0.0f;

    // each of 256 threads copies 2x16B for A and 2x16B for B per k-chunk
#define ISSUE_TILE(KT, BUF)                                                          \
    {                                                                                \
        const int k0_ = (KT) * BK;                                                   \
        _Pragma("unroll")                                                            \
        for (int it_ = 0; it_ < 2; it_++) {                                          \
            int c_   = tid + it_ * 256;                                              \
            int row_ = c_ >> 2;                                                      \
            int kc_  = (c_ & 3) << 3;                                                \
            unsigned da_ = sptr(&sA[(BUF)][row_ * LDSW + kc_]);                      \
            asm volatile("cp.async.cg.shared.global [%0], [%1], 16;\n"               \
                         :: "r"(da_), "l"(gA + (size_t)row_ * D_DIM + k0_ + kc_));   \
            unsigned db_ = sptr(&sB[(BUF)][row_ * LDSW + kc_]);                      \
            asm volatile("cp.async.cg.shared.global [%0], [%1], 16;\n"               \
                         :: "r"(db_), "l"(gB + (size_t)row_ * D_DIM + k0_ + kc_));   \
        }                                                                            \
        asm volatile("cp.async.commit_group;\n");                                    \
    }

    ISSUE_TILE(0, 0);

    for (int kt = 0; kt < KT_ITERS; kt++) {
        const int buf = kt & 1;
        if (kt + 1 < KT_ITERS) {
            ISSUE_TILE(kt + 1, (kt + 1) & 1);
            asm volatile("cp.async.wait_group 1;\n");
        } else {
            asm volatile("cp.async.wait_group 0;\n");
        }
        __syncthreads();

        #pragma unroll
        for (int ks = 0; ks < 2; ks++) {
            uint32_t ar[4][4];
            #pragma unroll
            for (int mf = 0; mf < 4; mf++) {
                int row  = wm * 64 + mf * 16 + (lane & 15);
                int koff = ks * 16 + ((lane >> 4) & 1) * 8;
                unsigned addr = sptr(&sA[buf][row * LDSW + koff]);
                asm volatile("ldmatrix.sync.aligned.m8n8.x4.shared.b16 {%0,%1,%2,%3}, [%4];\n"
                             : "=r"(ar[mf][0]), "=r"(ar[mf][1]),
                               "=r"(ar[mf][2]), "=r"(ar[mf][3])
                             : "r"(addr));
            }
            uint32_t br[4][2];
            #pragma unroll
            for (int nf = 0; nf < 4; nf++) {
                int rowb = wn * 32 + nf * 8 + (lane & 7);
                int koff = ks * 16 + ((lane >> 3) & 1) * 8;
                unsigned addr = sptr(&sB[buf][rowb * LDSW + koff]);
                asm volatile("ldmatrix.sync.aligned.m8n8.x2.shared.b16 {%0,%1}, [%2];\n"
                             : "=r"(br[nf][0]), "=r"(br[nf][1]) : "r"(addr));
            }
            #pragma unroll
            for (int mf = 0; mf < 4; mf++)
                #pragma unroll
                for (int nf = 0; nf < 4; nf++)
                    asm volatile(
                        "mma.sync.aligned.m16n8k16.row.col.f32.bf16.bf16.f32 "
                        "{%0,%1,%2,%3},{%4,%5,%6,%7},{%8,%9},{%0,%1,%2,%3};\n"
                        : "+f"(acc[mf][nf][0]), "+f"(acc[mf][nf][1]),
                          "+f"(acc[mf][nf][2]), "+f"(acc[mf][nf][3])
                        : "r"(ar[mf][0]), "r"(ar[mf][1]), "r"(ar[mf][2]), "r"(ar[mf][3]),
                          "r"(br[nf][0]), "r"(br[nf][1]));
        }
        __syncthreads();
    }
#undef ISSUE_TILE

    // epilogue: write fp32 scores
    #pragma unroll
    for (int mf = 0; mf < 4; mf++) {
        #pragma unroll
        for (int nf = 0; nf < 4; nf++) {
            int row = bm + wm * 64 + mf * 16 + (lane >> 2);
            int col = bn + wn * 32 + nf * 8 + (lane & 3) * 2;
            float2 v01 = make_float2(acc[mf][nf][0], acc[mf][nf][1]);
            float2 v23 = make_float2(acc[mf][nf][2], acc[mf][nf][3]);
            *reinterpret_cast<float2*>(&g_scores[(size_t)row * P + col])       = v01;
            *reinterpret_cast<float2*>(&g_scores[(size_t)(row + 8) * P + col]) = v23;
        }
    }
}

// ---------------------------------------------------------------------------
// One block per query row: online logsumexp + count(> s_target), then weighted loss.
__global__ __launch_bounds__(256) void reduce_kernel(int P, int NP) {
    const int row = blockIdx.x;
    const int tid = threadIdx.x;
    const float* __restrict__ s = g_scores + (size_t)row * P;

    __shared__ float st_sh;
    if (tid == 0) st_sh = s[row * NP];   // target column = row * n_passages
    __syncthreads();
    const float st = st_sh;

    float m = -1e30f, sum = 0.0f;
    int cnt = 0;

    const float4* s4 = reinterpret_cast<const float4*>(s);
    const int n4 = P >> 2;
    for (int i = tid; i < n4; i += 256) {
        float4 v = s4[i];
        #pragma unroll
        for (int j = 0; j < 4; j++) {
            float x = (j == 0) ? v.x : (j == 1) ? v.y : (j == 2) ? v.z : v.w;
            if (x > m) { sum = sum * __expf(m - x) + 1.0f; m = x; }
            else       { sum += __expf(x - m); }
            cnt += (x > st);
        }
    }

    __shared__ float rm[256];
    __shared__ float rs[256];
    __shared__ int   rc[256];
    rm[tid] = m; rs[tid] = sum; rc[tid] = cnt;
    __syncthreads();
    for (int off = 128; off > 0; off >>= 1) {
        if (tid < off) {
            float m2 = rm[tid + off], s2 = rs[tid + off];
            float m1 = rm[tid],       s1 = rs[tid];
            float mm = fmaxf(m1, m2);
            rs[tid] = s1 * __expf(m1 - mm) + s2 * __expf(m2 - mm);
            rm[tid] = mm;
            rc[tid] += rc[tid + off];
        }
        __syncthreads();
    }

    if (tid == 0) {
        float lse = rm[0] + logf(rs[0]);
        float raw = lse - st;                       // -log_softmax at target
        float r   = (float)rc[0];                   // rank of positive (descending)
        float d   = r - 1.0f;                       // OPTIMAL_RANK = 1.0
        float w   = 1.0f + 2.6f * __expf(-(d * d) / (2.0f * 1.8f * 1.8f));
        atomicAdd(&g_loss_sum, (double)(raw * w));
    }
}

__global__ void final_kernel(float* __restrict__ out, int Bq) {
    out[0] = (float)(g_loss_sum / (double)Bq);
}

// ---------------------------------------------------------------------------
extern "C" void kernel_launch(void* const* d_in, const int* in_sizes, int n_in,
                              void* d_out, int out_size) {
    const float* q = (const float*)d_in[0];
    const float* p = (const float*)d_in[1];
    const int nq = in_sizes[0];            // B * D
    const int np = in_sizes[1];            // P * D
    const int Bq = nq / D_DIM;             // 2048
    const int P  = np / D_DIM;             // 16384
    const int NP = P / Bq;                 // 8

    const int ntot = nq + np;
    convert_kernel<<<(ntot + 255) / 256, 256>>>(q, p, nq, ntot);
    init_kernel<<<1, 1>>>();

    dim3 grid(P / BN, Bq / BM);            // (128, 16)
    gemm_kernel<<<grid, 256>>>(P);

    reduce_kernel<<<Bq, 256>>>(P, NP);
    final_kernel<<<1, 1>>>((float*)d_out, Bq);
}

// round 6
// speedup vs baseline: 1.4033x; 1.4033x over previous
#include <cuda_runtime.h>
#include <cuda_bf16.h>
#include <cstdint>

// Shapes: B=2048, D=768, P=16384, NP=8
#define D_DIM 768
#define BM 128
#define BN 128
#define BK 32
#define LDSW 40                 // padded smem row stride (80B) -> conflict-free ldmatrix/STS
#define KT_ITERS (D_DIM / BK)   // 24

// ---- scratch ----
__device__ __nv_bfloat16 g_qb[2048 * 768];
__device__ __nv_bfloat16 g_pb[16384 * 768];
__device__ float  g_st[2048];
__device__ double g_sum[2048];
__device__ int    g_cnt[2048];

// ===========================================================================
__global__ void convert_kernel(const float* __restrict__ q, const float* __restrict__ p,
                               int nq4, int ntot4) {
    int i = blockIdx.x * blockDim.x + threadIdx.x;
    if (i >= ntot4) return;
    float4 v;
    __nv_bfloat16* dst;
    if (i < nq4) { v = reinterpret_cast<const float4*>(q)[i]; dst = g_qb + i * 4; }
    else         { v = reinterpret_cast<const float4*>(p)[i - nq4]; dst = g_pb + (size_t)(i - nq4) * 4; }
    uint2 o;
    o.x = ((uint32_t)__bfloat16_as_ushort(__float2bfloat16(v.x))) |
          ((uint32_t)__bfloat16_as_ushort(__float2bfloat16(v.y)) << 16);
    o.y = ((uint32_t)__bfloat16_as_ushort(__float2bfloat16(v.z))) |
          ((uint32_t)__bfloat16_as_ushort(__float2bfloat16(v.w)) << 16);
    *reinterpret_cast<uint2*>(dst) = o;
}

__global__ void init_kernel(int Bq) {
    int i = blockIdx.x * blockDim.x + threadIdx.x;
    if (i < Bq) { g_sum[i] = 0.0; g_cnt[i] = 0; }
}

// st[r] = dot(qb[r], pb[8r]) in fp32 — one warp per row.
__global__ __launch_bounds__(256) void st_kernel(int Bq, int NP) {
    int warp = (blockIdx.x * blockDim.x + threadIdx.x) >> 5;
    int lane = threadIdx.x & 31;
    if (warp >= Bq) return;
    const uint4* qa = reinterpret_cast<const uint4*>(g_qb + (size_t)warp * D_DIM);
    const uint4* pa = reinterpret_cast<const uint4*>(g_pb + (size_t)warp * NP * D_DIM);
    float acc = 0.0f;
    #pragma unroll
    for (int i = 0; i < 3; i++) {                  // 96 uint4 per row
        uint4 a = qa[lane + 32 * i];
        uint4 b = pa[lane + 32 * i];
        const uint32_t* au = &a.x;
        const uint32_t* bu = &b.x;
        #pragma unroll
        for (int j = 0; j < 4; j++) {
            float2 fa = __bfloat1622float2(*reinterpret_cast<const __nv_bfloat162*>(&au[j]));
            float2 fb = __bfloat1622float2(*reinterpret_cast<const __nv_bfloat162*>(&bu[j]));
            acc = fmaf(fa.x, fb.x, acc);
            acc = fmaf(fa.y, fb.y, acc);
        }
    }
    #pragma unroll
    for (int off = 16; off > 0; off >>= 1)
        acc += __shfl_xor_sync(0xFFFFFFFF, acc, off);
    if (lane == 0) g_st[warp] = acc;
}

__device__ __forceinline__ unsigned sptr(const void* p) {
    return (unsigned)__cvta_generic_to_shared(p);
}

// ---------------------------------------------------------------------------
// Fused GEMM + per-row (max, sumexp, count>st) reduction.
// CTA 128x128, 4 warps (2x2), warp tile 64x64, k-chunk 32, double-buffered cp.async.
__global__ __launch_bounds__(128, 2) void gemm_fused(int P) {
    __shared__ __nv_bfloat16 sA[2][BM * LDSW];
    __shared__ __nv_bfloat16 sB[2][BN * LDSW];
    __shared__ float red_m[2][BM];
    __shared__ float red_s[2][BM];
    __shared__ int   red_c[2][BM];

    const int tid  = threadIdx.x;
    const int lane = tid & 31;
    const int warp = tid >> 5;
    const int wm   = warp >> 1;   // 0..1 -> 64 rows
    const int wn   = warp & 1;    // 0..1 -> 64 cols
    const int bm   = blockIdx.y * BM;
    const int bn   = blockIdx.x * BN;

    const __nv_bfloat16* gA = g_qb + (size_t)bm * D_DIM;
    const __nv_bfloat16* gB = g_pb + (size_t)bn * D_DIM;

    float acc[4][8][4];
    #pragma unroll
    for (int a = 0; a < 4; a++)
        #pragma unroll
        for (int b = 0; b < 8; b++)
            #pragma unroll
            for (int c = 0; c < 4; c++) acc[a][b][c] = 0.0f;

    // 128 threads copy 4x16B for A and 4x16B for B per k-chunk
#define ISSUE_TILE(KT, BUF)                                                          \
    {                                                                                \
        const int k0_ = (KT) * BK;                                                   \
        _Pragma("unroll")                                                            \
        for (int it_ = 0; it_ < 4; it_++) {                                          \
            int c_   = tid + it_ * 128;                                              \
            int row_ = c_ >> 2;                                                      \
            int kc_  = (c_ & 3) << 3;                                                \
            unsigned da_ = sptr(&sA[(BUF)][row_ * LDSW + kc_]);                      \
            asm volatile("cp.async.cg.shared.global [%0], [%1], 16;\n"               \
                         :: "r"(da_), "l"(gA + (size_t)row_ * D_DIM + k0_ + kc_));   \
            unsigned db_ = sptr(&sB[(BUF)][row_ * LDSW + kc_]);                      \
            asm volatile("cp.async.cg.shared.global [%0], [%1], 16;\n"               \
                         :: "r"(db_), "l"(gB + (size_t)row_ * D_DIM + k0_ + kc_));   \
        }                                                                            \
        asm volatile("cp.async.commit_group;\n");                                    \
    }

    ISSUE_TILE(0, 0);

    for (int kt = 0; kt < KT_ITERS; kt++) {
        const int buf = kt & 1;
        if (kt + 1 < KT_ITERS) {
            ISSUE_TILE(kt + 1, (kt + 1) & 1);
            asm volatile("cp.async.wait_group 1;\n");
        } else {
            asm volatile("cp.async.wait_group 0;\n");
        }
        __syncthreads();

        #pragma unroll
        for (int ks = 0; ks < 2; ks++) {
            uint32_t ar[4][4];
            #pragma unroll
            for (int mf = 0; mf < 4; mf++) {
                int row  = wm * 64 + mf * 16 + (lane & 15);
                int koff = ks * 16 + ((lane >> 4) & 1) * 8;
                unsigned addr = sptr(&sA[buf][row * LDSW + koff]);
                asm volatile("ldmatrix.sync.aligned.m8n8.x4.shared.b16 {%0,%1,%2,%3}, [%4];\n"
                             : "=r"(ar[mf][0]), "=r"(ar[mf][1]),
                               "=r"(ar[mf][2]), "=r"(ar[mf][3])
                             : "r"(addr));
            }
            uint32_t br[4][4];
            #pragma unroll
            for (int nf2 = 0; nf2 < 4; nf2++) {
                int rowb = wn * 64 + nf2 * 16 + (lane & 7) + ((lane >> 4) & 1) * 8;
                int koff = ks * 16 + ((lane >> 3) & 1) * 8;
                unsigned addr = sptr(&sB[buf][rowb * LDSW + koff]);
                asm volatile("ldmatrix.sync.aligned.m8n8.x4.shared.b16 {%0,%1,%2,%3}, [%4];\n"
                             : "=r"(br[nf2][0]), "=r"(br[nf2][1]),
                               "=r"(br[nf2][2]), "=r"(br[nf2][3])
                             : "r"(addr));
            }
            #pragma unroll
            for (int mf = 0; mf < 4; mf++)
                #pragma unroll
                for (int nf2 = 0; nf2 < 4; nf2++) {
                    asm volatile(
                        "mma.sync.aligned.m16n8k16.row.col.f32.bf16.bf16.f32 "
                        "{%0,%1,%2,%3},{%4,%5,%6,%7},{%8,%9},{%0,%1,%2,%3};\n"
                        : "+f"(acc[mf][nf2 * 2][0]), "+f"(acc[mf][nf2 * 2][1]),
                          "+f"(acc[mf][nf2 * 2][2]), "+f"(acc[mf][nf2 * 2][3])
                        : "r"(ar[mf][0]), "r"(ar[mf][1]), "r"(ar[mf][2]), "r"(ar[mf][3]),
                          "r"(br[nf2][0]), "r"(br[nf2][1]));
                    asm volatile(
                        "mma.sync.aligned.m16n8k16.row.col.f32.bf16.bf16.f32 "
                        "{%0,%1,%2,%3},{%4,%5,%6,%7},{%8,%9},{%0,%1,%2,%3};\n"
                        : "+f"(acc[mf][nf2 * 2 + 1][0]), "+f"(acc[mf][nf2 * 2 + 1][1]),
                          "+f"(acc[mf][nf2 * 2 + 1][2]), "+f"(acc[mf][nf2 * 2 + 1][3])
                        : "r"(ar[mf][0]), "r"(ar[mf][1]), "r"(ar[mf][2]), "r"(ar[mf][3]),
                          "r"(br[nf2][2]), "r"(br[nf2][3]));
                }
        }
        __syncthreads();
    }
#undef ISSUE_TILE

    // ---- fused epilogue: per-row (max, sumexp, count > st) over this CTA's 128 cols ----
    #pragma unroll
    for (int mf = 0; mf < 4; mf++) {
        #pragma unroll
        for (int rh = 0; rh < 2; rh++) {
            const int row_local = wm * 64 + mf * 16 + rh * 8 + (lane >> 2);
            const float st = g_st[bm + row_local];

            float mloc = -1e30f;
            #pragma unroll
            for (int nf = 0; nf < 8; nf++) {
                mloc = fmaxf(mloc, acc[mf][nf][rh * 2]);
                mloc = fmaxf(mloc, acc[mf][nf][rh * 2 + 1]);
            }
            float ssum = 0.0f;
            int cnt = 0;
            #pragma unroll
            for (int nf = 0; nf < 8; nf++) {
                float x0 = acc[mf][nf][rh * 2];
                float x1 = acc[mf][nf][rh * 2 + 1];
                ssum += __expf(x0 - mloc) + __expf(x1 - mloc);
                cnt  += (x0 > st) + (x1 > st);
            }
            // merge across the 4 lanes sharing this row (lane&3)
            #pragma unroll
            for (int w = 1; w <= 2; w <<= 1) {
                float m2 = __shfl_xor_sync(0xFFFFFFFF, mloc, w);
                float s2 = __shfl_xor_sync(0xFFFFFFFF, ssum, w);
                int   c2 = __shfl_xor_sync(0xFFFFFFFF, cnt,  w);
                float mm = fmaxf(mloc, m2);
                ssum = ssum * __expf(mloc - mm) + s2 * __expf(m2 - mm);
                mloc = mm;
                cnt += c2;
            }
            if ((lane & 3) == 0) {
                red_m[wn][row_local] = mloc;
                red_s[wn][row_local] = ssum;
                red_c[wn][row_local] = cnt;
            }
        }
    }
    __syncthreads();

    if (tid < BM) {
        const int row = bm + tid;
        float m0 = red_m[0][tid], s0 = red_s[0][tid];
        float m1 = red_m[1][tid], s1 = red_s[1][tid];
        float mm = fmaxf(m0, m1);
        float ss = s0 * __expf(m0 - mm) + s1 * __expf(m1 - mm);
        int   cc = red_c[0][tid] + red_c[1][tid];
        // exact (to double precision) global merge: sum of exp(x) in double
        double val = (double)ss * exp((double)mm);
        atomicAdd(&g_sum[row], val);
        atomicAdd(&g_cnt[row], cc);
    }
}

// ---------------------------------------------------------------------------
__global__ __launch_bounds__(256) void final_kernel(float* __restrict__ out, int Bq) {
    __shared__ double sh[256];
    const int tid = threadIdx.x;
    double accum = 0.0;
    for (int r = tid; r < Bq; r += 256) {
        double lse = log(g_sum[r]);
        double raw = lse - (double)g_st[r];
        float rank = (float)g_cnt[r];
        float d = rank - 1.0f;                       // OPTIMAL_RANK = 1.0
        float w = 1.0f + 2.6f * __expf(-(d * d) / (2.0f * 1.8f * 1.8f));
        accum += raw * (double)w;
    }
    sh[tid] = accum;
    __syncthreads();
    for (int off = 128; off > 0; off >>= 1) {
        if (tid < off) sh[tid] += sh[tid + off];
        __syncthreads();
    }
    if (tid == 0) out[0] = (float)(sh[0] / (double)Bq);
}

// ---------------------------------------------------------------------------
extern "C" void kernel_launch(void* const* d_in, const int* in_sizes, int n_in,
                              void* d_out, int out_size) {
    const float* q = (const float*)d_in[0];
    const float* p = (const float*)d_in[1];
    const int nq = in_sizes[0];            // B * D
    const int np = in_sizes[1];            // P * D
    const int Bq = nq / D_DIM;             // 2048
    const int P  = np / D_DIM;             // 16384
    const int NP = P / Bq;                 // 8

    const int nq4 = nq / 4, ntot4 = (nq + np) / 4;
    convert_kernel<<<(ntot4 + 255) / 256, 256>>>(q, p, nq4, ntot4);
    init_kernel<<<(Bq + 255) / 256, 256>>>(Bq);
    st_kernel<<<(Bq * 32 + 255) / 256, 256>>>(Bq, NP);

    dim3 grid(P / BN, Bq / BM);            // (128, 16)
    gemm_fused<<<grid, 128>>>(P);

    final_kernel<<<1, 256>>>((float*)d_out, Bq);
}